// round 5
// baseline (speedup 1.0000x reference)
#include <cuda_runtime.h>
#include <cstdint>

#define LOG2E 1.4426950408889634f
#define NPTS 4096

#define FMA2(a, b, c) \
    asm("fma.rn.f32x2 %0, %1, %2, %0;" : "+l"(a) : "l"(b), "l"(c))

// Fused single-kernel RBF covariance:
//   cov[i,j] = exp2( sum_d U[i,d]*V[j,d] + c_i + d_j )
// with U = x/scale, V = log2e * xx/scale,
//      c_i = -0.5*log2e*||u_i||^2, d_j = -0.5*log2e*||v_j||^2 + log2(var).
// 128x128 tile per CTA, 256 threads, 8x8 outputs/thread, packed fp32x2 FMA.
__global__ void __launch_bounds__(256, 2) rbf_fused(
    const float* __restrict__ x,         // [4096,16]
    const float* __restrict__ xx,        // [4096,16]
    const float* __restrict__ scale_ff,  // [16]
    const float* __restrict__ var_ff,    // scalar
    float* __restrict__ out)             // [4096,4096]
{
    __shared__ __align__(16) float Ud[16][256];  // duplicated pairs: Ud[d][2i]=Ud[d][2i+1]
    __shared__ __align__(16) float Vs[16][128];
    __shared__ float cs[128];
    __shared__ float dsm[128];
    __shared__ float s_inv[16];
    __shared__ float s_l2var;

    const int tid = threadIdx.x;
    const int tx = tid & 15;
    const int ty = tid >> 4;
    // consecutive blockIdx.x -> adjacent j-stripes of the same i-rows (L2 locality)
    const int bi0 = blockIdx.y * 128;
    const int bj0 = blockIdx.x * 128;

    // ---- phase 0: kernel params (softplus) computed once into smem ----
    if (tid < 16) {
        float s = log1pf(__expf(scale_ff[tid]));
        s_inv[tid] = 1.0f / s;
    } else if (tid == 16) {
        s_l2var = log2f(log1pf(__expf(var_ff[0])));
    }
    __syncthreads();

    // ---- phase 1: build U/V tiles + row/col norms (fused preproc) ----
    if (tid < 128) {
        const float4* row = (const float4*)(x + (size_t)(bi0 + tid) * 16);
        float4 a = row[0], b = row[1], c4 = row[2], e = row[3];
        float v[16] = {a.x, a.y, a.z, a.w, b.x, b.y, b.z, b.w,
                       c4.x, c4.y, c4.z, c4.w, e.x, e.y, e.z, e.w};
        float s2 = 0.0f;
#pragma unroll
        for (int d = 0; d < 16; d++) {
            float u = v[d] * s_inv[d];
            ((float2*)&Ud[d][0])[tid] = make_float2(u, u);
            s2 = fmaf(u, u, s2);
        }
        cs[tid] = -0.5f * LOG2E * s2;
    } else {
        const int j = tid - 128;
        const float4* row = (const float4*)(xx + (size_t)(bj0 + j) * 16);
        float4 a = row[0], b = row[1], c4 = row[2], e = row[3];
        float v[16] = {a.x, a.y, a.z, a.w, b.x, b.y, b.z, b.w,
                       c4.x, c4.y, c4.z, c4.w, e.x, e.y, e.z, e.w};
        float s2 = 0.0f;
#pragma unroll
        for (int d = 0; d < 16; d++) {
            float u = v[d] * s_inv[d];
            Vs[d][j] = LOG2E * u;
            s2 = fmaf(u, u, s2);
        }
        dsm[j] = -0.5f * LOG2E * s2 + s_l2var;
    }
    __syncthreads();

    // ---- accumulator init: acc = c_i + d_j ----
    float cv[8], dv8[8];
#pragma unroll
    for (int r = 0; r < 4; r++) {
        cv[r]      = cs[ty * 4 + r];
        cv[4 + r]  = cs[64 + ty * 4 + r];
        dv8[r]     = dsm[tx * 4 + r];
        dv8[4 + r] = dsm[64 + tx * 4 + r];
    }
    unsigned long long acc[8][4];
#pragma unroll
    for (int ii = 0; ii < 8; ii++) {
#pragma unroll
        for (int jp = 0; jp < 4; jp++) {
            float lo = cv[ii] + dv8[2 * jp];
            float hi = cv[ii] + dv8[2 * jp + 1];
            asm("mov.b64 %0, {%1, %2};" : "=l"(acc[ii][jp]) : "f"(lo), "f"(hi));
        }
    }

    // ---- mainloop: D=16 fully unrolled; LDS.128 results feed fma.rn.f32x2
    //      directly (no copy arrays -> no register-pair MOV traffic) ----
#pragma unroll
    for (int d = 0; d < 16; d++) {
        const ulonglong2* up = (const ulonglong2*)&Ud[d][0];   // 16B units
        const ulonglong2* vp = (const ulonglong2*)&Vs[d][0];
        ulonglong2 u0 = up[2 * ty];          // dup(i0),dup(i1)
        ulonglong2 u1 = up[2 * ty + 1];      // dup(i2),dup(i3)
        ulonglong2 u2 = up[32 + 2 * ty];     // dup(i4),dup(i5)
        ulonglong2 u3 = up[33 + 2 * ty];     // dup(i6),dup(i7)
        ulonglong2 va = vp[tx];              // (j0,j1),(j2,j3)
        ulonglong2 vb = vp[16 + tx];         // (j4,j5),(j6,j7)

        FMA2(acc[0][0], u0.x, va.x); FMA2(acc[0][1], u0.x, va.y);
        FMA2(acc[0][2], u0.x, vb.x); FMA2(acc[0][3], u0.x, vb.y);
        FMA2(acc[1][0], u0.y, va.x); FMA2(acc[1][1], u0.y, va.y);
        FMA2(acc[1][2], u0.y, vb.x); FMA2(acc[1][3], u0.y, vb.y);
        FMA2(acc[2][0], u1.x, va.x); FMA2(acc[2][1], u1.x, va.y);
        FMA2(acc[2][2], u1.x, vb.x); FMA2(acc[2][3], u1.x, vb.y);
        FMA2(acc[3][0], u1.y, va.x); FMA2(acc[3][1], u1.y, va.y);
        FMA2(acc[3][2], u1.y, vb.x); FMA2(acc[3][3], u1.y, vb.y);
        FMA2(acc[4][0], u2.x, va.x); FMA2(acc[4][1], u2.x, va.y);
        FMA2(acc[4][2], u2.x, vb.x); FMA2(acc[4][3], u2.x, vb.y);
        FMA2(acc[5][0], u2.y, va.x); FMA2(acc[5][1], u2.y, va.y);
        FMA2(acc[5][2], u2.y, vb.x); FMA2(acc[5][3], u2.y, vb.y);
        FMA2(acc[6][0], u3.x, va.x); FMA2(acc[6][1], u3.x, va.y);
        FMA2(acc[6][2], u3.x, vb.x); FMA2(acc[6][3], u3.x, vb.y);
        FMA2(acc[7][0], u3.y, va.x); FMA2(acc[7][1], u3.y, va.y);
        FMA2(acc[7][2], u3.y, vb.x); FMA2(acc[7][3], u3.y, vb.y);
    }

    // ---- epilogue: exp2 via MUFU.EX2, float4 stores ----
#pragma unroll
    for (int ii = 0; ii < 8; ii++) {
        int ig = bi0 + ((ii < 4) ? (ty * 4 + ii) : (64 + ty * 4 + (ii - 4)));
        float f[8];
#pragma unroll
        for (int jp = 0; jp < 4; jp++) {
            float lo, hi;
            asm("mov.b64 {%0, %1}, %2;" : "=f"(lo), "=f"(hi) : "l"(acc[ii][jp]));
            asm("ex2.approx.ftz.f32 %0, %0;" : "+f"(lo));
            asm("ex2.approx.ftz.f32 %0, %0;" : "+f"(hi));
            f[2 * jp]     = lo;
            f[2 * jp + 1] = hi;
        }
        float4 o0 = make_float4(f[0], f[1], f[2], f[3]);
        float4 o1 = make_float4(f[4], f[5], f[6], f[7]);
        *(float4*)&out[(size_t)ig * NPTS + bj0 + 4 * tx]      = o0;
        *(float4*)&out[(size_t)ig * NPTS + bj0 + 64 + 4 * tx] = o1;
    }
}

extern "C" void kernel_launch(void* const* d_in, const int* in_sizes, int n_in,
                              void* d_out, int out_size) {
    const float* x        = (const float*)d_in[0];
    const float* xx       = (const float*)d_in[1];
    const float* scale_ff = (const float*)d_in[2];
    const float* var_ff   = (const float*)d_in[3];
    float* out = (float*)d_out;

    dim3 grid(NPTS / 128, NPTS / 128);
    rbf_fused<<<grid, 256>>>(x, xx, scale_ff, var_ff, out);
}